// round 11
// baseline (speedup 1.0000x reference)
#include <cuda_runtime.h>
#include <cstdint>

#define B_ROWS 16384
#define M_DIM  256
#define N_DIM  1024
#define DEPTH  16

// ---------------------------------------------------------------------------
// Scratch (__device__ globals per allocation-free rule)
// hi arrays hold fp32 bit patterns with low-13 mantissa cleared (tf32-exact);
// lo arrays hold fp32 bit patterns of (x - hi).
// ---------------------------------------------------------------------------
__device__ float    g_v [(size_t)B_ROWS * N_DIM];            // 64 MB
__device__ uint32_t g_uh[(size_t)B_ROWS * N_DIM];            // 64 MB
__device__ uint32_t g_ul[(size_t)B_ROWS * N_DIM];            // 64 MB
__device__ uint32_t g_rh[(size_t)B_ROWS * M_DIM];            // 16 MB
__device__ uint32_t g_rl[(size_t)B_ROWS * M_DIM];            // 16 MB
__device__ uint32_t g_xh[(size_t)B_ROWS * M_DIM];            // 16 MB
__device__ uint32_t g_xl[(size_t)B_ROWS * M_DIM];            // 16 MB
__device__ uint32_t g_Ah[(size_t)M_DIM * N_DIM];             //  1 MB
__device__ uint32_t g_Al[(size_t)M_DIM * N_DIM];             //  1 MB
__device__ uint32_t g_Wh[(size_t)DEPTH * N_DIM * M_DIM];     // 16 MB
__device__ uint32_t g_Wl[(size_t)DEPTH * N_DIM * M_DIM];     // 16 MB

// ---------------------------------------------------------------------------
// helpers
// ---------------------------------------------------------------------------
__device__ __forceinline__ uint32_t smem_u32(const void* p) {
    uint32_t a;
    asm("{ .reg .u64 t; cvta.to.shared.u64 t, %1; cvt.u32.u64 %0, t; }"
        : "=r"(a) : "l"(p));
    return a;
}

// .cg: L2-only, keep L1 for fragment reads
#define CP_ASYNC_16(dst, src) \
    asm volatile("cp.async.cg.shared.global [%0], [%1], 16;" \
                 :: "r"(dst), "l"(src) : "memory")
#define CP_COMMIT() asm volatile("cp.async.commit_group;" ::: "memory")

__device__ __forceinline__ uint32_t tf32_hi(float x) {
    uint32_t h;
    asm("cvt.rna.tf32.f32 %0, %1;" : "=r"(h) : "f"(x));
    return h;
}
__device__ __forceinline__ void split2(float x, uint32_t& h, uint32_t& l) {
    h = tf32_hi(x);
    l = __float_as_uint(x - __uint_as_float(h));
}

__device__ __forceinline__ void mma_tf32(float* c, const uint32_t* a,
                                         const uint32_t* b) {
    asm volatile(
        "mma.sync.aligned.m16n8k8.row.col.f32.tf32.tf32.f32 "
        "{%0,%1,%2,%3}, {%4,%5,%6,%7}, {%8,%9}, {%0,%1,%2,%3};"
        : "+f"(c[0]), "+f"(c[1]), "+f"(c[2]), "+f"(c[3])
        : "r"(a[0]), "r"(a[1]), "r"(a[2]), "r"(a[3]), "r"(b[0]), "r"(b[1]));
}

// ---------------------------------------------------------------------------
// One-shot operand split: hi/lo arrays for A, W, x
// ---------------------------------------------------------------------------
__global__ void __launch_bounds__(256)
split_kernel(const float* __restrict__ src, uint32_t* __restrict__ hi,
             uint32_t* __restrict__ lo, int n4)
{
    const int i = blockIdx.x * 256 + threadIdx.x;
    if (i >= n4) return;
    const float4 v = reinterpret_cast<const float4*>(src)[i];
    uint4 h, l;
    split2(v.x, h.x, l.x);
    split2(v.y, h.y, l.y);
    split2(v.z, h.z, l.z);
    split2(v.w, h.w, l.w);
    reinterpret_cast<uint4*>(hi)[i] = h;
    reinterpret_cast<uint4*>(lo)[i] = l;
}

// ---------------------------------------------------------------------------
// Smem stage (BK=32): 4 tiles (Ahi, Alo, Bhi, Blo), each 128 rows x 32 k u32
// (16 KB), k-interleaved: word offset(kblk, m, klo) = kblk*512 +
// ((m^kblk)<<2) + klo, kblk = (k%32)/4 in [0,8), klo = k%4. The XOR is a
// permutation of 16B slots within each kblk -> conflict-free cp.async stores;
// fragment LDS spreads a warp over 32 distinct banks (validated in R9).
// Stage = 4 x 4096 u32 = 64 KB; double-buffered = 128 KB/CTA -> 1 CTA/SM.
// ---------------------------------------------------------------------------
template<int KTOT>
__device__ __forceinline__ void stage_load(const uint32_t* __restrict__ Ph,
                                           const uint32_t* __restrict__ Pl,
                                           const uint32_t* __restrict__ Qh,
                                           const uint32_t* __restrict__ Ql,
                                           int i0, int j0, int kt,
                                           uint32_t sbase_bytes)
{
    const int tid = threadIdx.x;
    const int k0 = kt * 32;
    const uint32_t stage = sbase_bytes + (uint32_t)((kt & 1) * 65536);
#pragma unroll
    for (int rep = 0; rep < 4; ++rep) {
        const int c  = tid + 256 * rep;     // chunk id 0..1023
        const int m  = c >> 3;              // 0..127
        const int kb = c & 7;               // 0..7
        const uint32_t off = (uint32_t)((kb << 11) + ((m ^ kb) << 4));
        const size_t pi = (size_t)(i0 + m) * KTOT + k0 + kb * 4;
        const size_t qi = (size_t)(j0 + m) * KTOT + k0 + kb * 4;
        CP_ASYNC_16(stage + off,           Ph + pi);
        CP_ASYNC_16(stage + 16384u + off,  Pl + pi);
        CP_ASYNC_16(stage + 32768u + off,  Qh + qi);
        CP_ASYNC_16(stage + 49152u + off,  Ql + qi);
    }
    CP_COMMIT();
}

// ---------------------------------------------------------------------------
// 3xTF32 NT GEMM: C[i,j] = aux[i,j] (+/-) sum_k P[i,k]*Q[j,k]
// CTA 128x128, BK=32, 256 threads, warp tile 64x32 (warp grid 2m x 4n).
// Operands pre-split in gmem; inner loop is pure LDS + HMMA (no ALU).
// SPLITOUT: additionally write tf32-split hi/lo of the result.
// ---------------------------------------------------------------------------
template<int KTOT, bool SUB, bool SPLITOUT>
__device__ __forceinline__ void mma_gemm_body(const uint32_t* __restrict__ Ph,
                                              const uint32_t* __restrict__ Pl,
                                              const uint32_t* __restrict__ Qh,
                                              const uint32_t* __restrict__ Ql,
                                              const float* __restrict__ aux,
                                              float* __restrict__ C,
                                              uint32_t* __restrict__ Chi,
                                              uint32_t* __restrict__ Clo,
                                              const int ldc)
{
    extern __shared__ __align__(16) uint32_t sm[];   // 2 stages x 16384 u32

    const int tid  = threadIdx.x;
    const int lane = tid & 31;
    const int w    = tid >> 5;
    const int g    = lane >> 2;
    const int t    = lane & 3;
    const int i0   = blockIdx.y * 128;
    const int j0   = blockIdx.x * 128;
    const int wm   = (w >> 2) * 64;
    const int wn   = (w & 3) * 32;

    const uint32_t sbase = smem_u32(sm);

    float acc[4][4][4];
#pragma unroll
    for (int a = 0; a < 4; ++a)
#pragma unroll
        for (int b = 0; b < 4; ++b)
#pragma unroll
            for (int c = 0; c < 4; ++c) acc[a][b][c] = 0.0f;

    constexpr int NSTAGE = KTOT / 32;
    stage_load<KTOT>(Ph, Pl, Qh, Ql, i0, j0, 0, sbase);

#pragma unroll 1
    for (int kt = 0; kt < NSTAGE; ++kt) {
        if (kt + 1 < NSTAGE) {
            stage_load<KTOT>(Ph, Pl, Qh, Ql, i0, j0, kt + 1, sbase);
            asm volatile("cp.async.wait_group 1;" ::: "memory");
        } else {
            asm volatile("cp.async.wait_group 0;" ::: "memory");
        }
        __syncthreads();

        const uint32_t* Ahs = sm + (kt & 1) * 16384;
        const uint32_t* Als = Ahs + 4096;
        const uint32_t* Bhs = Ahs + 8192;
        const uint32_t* Bls = Ahs + 12288;

#pragma unroll
        for (int ks = 0; ks < 4; ++ks) {       // four k8-pairs per stage
            const int kb0 = 2 * ks;
            const int kb1 = 2 * ks + 1;

            // A fragments: a0=(g,k=t) a1=(g+8,t) a2=(g,t+4) a3=(g+8,t+4)
            uint32_t ah[4][4], al[4][4];
#pragma unroll
            for (int mi = 0; mi < 4; ++mi) {
                const int m0 = wm + mi * 16 + g;
                const int m1 = m0 + 8;
                const int i00 = kb0 * 512 + ((m0 ^ kb0) << 2) + t;
                const int i01 = kb0 * 512 + ((m1 ^ kb0) << 2) + t;
                const int i10 = kb1 * 512 + ((m0 ^ kb1) << 2) + t;
                const int i11 = kb1 * 512 + ((m1 ^ kb1) << 2) + t;
                ah[mi][0] = Ahs[i00]; al[mi][0] = Als[i00];
                ah[mi][1] = Ahs[i01]; al[mi][1] = Als[i01];
                ah[mi][2] = Ahs[i10]; al[mi][2] = Als[i10];
                ah[mi][3] = Ahs[i11]; al[mi][3] = Als[i11];
            }
#pragma unroll
            for (int ni = 0; ni < 4; ++ni) {   // B loaded just-in-time
                const int n0 = wn + ni * 8 + g;
                const int j00 = kb0 * 512 + ((n0 ^ kb0) << 2) + t;
                const int j10 = kb1 * 512 + ((n0 ^ kb1) << 2) + t;
                uint32_t bh[2], bl[2];
                bh[0] = Bhs[j00]; bl[0] = Bls[j00];
                bh[1] = Bhs[j10]; bl[1] = Bls[j10];
#pragma unroll
                for (int mi = 0; mi < 4; ++mi) {
                    mma_tf32(acc[mi][ni], ah[mi], bh);   // hh
                    mma_tf32(acc[mi][ni], al[mi], bh);   // lh
                    mma_tf32(acc[mi][ni], ah[mi], bl);   // hl
                }
            }
        }
        __syncthreads();
    }

    // epilogue: y = aux +/- acc; write fp32 and/or tf32-split hi/lo
    // c0=(row g, col 2t) c1=(g,2t+1) c2=(g+8,2t) c3=(g+8,2t+1)
#pragma unroll
    for (int mi = 0; mi < 4; ++mi) {
        const int r0 = i0 + wm + mi * 16 + g;
#pragma unroll
        for (int ni = 0; ni < 4; ++ni) {
            const int col = j0 + wn + ni * 8 + 2 * t;
            const size_t o0 = (size_t)r0 * ldc + col;
            const size_t o1 = (size_t)(r0 + 8) * ldc + col;
            const float2 x0 = *reinterpret_cast<const float2*>(&aux[o0]);
            const float2 x1 = *reinterpret_cast<const float2*>(&aux[o1]);
            float2 y0, y1;
            if (SUB) {
                y0.x = x0.x - acc[mi][ni][0]; y0.y = x0.y - acc[mi][ni][1];
                y1.x = x1.x - acc[mi][ni][2]; y1.y = x1.y - acc[mi][ni][3];
            } else {
                y0.x = x0.x + acc[mi][ni][0]; y0.y = x0.y + acc[mi][ni][1];
                y1.x = x1.x + acc[mi][ni][2]; y1.y = x1.y + acc[mi][ni][3];
            }
            if (SPLITOUT) {
                uint2 h0, l0, h1, l1;
                split2(y0.x, h0.x, l0.x); split2(y0.y, h0.y, l0.y);
                split2(y1.x, h1.x, l1.x); split2(y1.y, h1.y, l1.y);
                *reinterpret_cast<uint2*>(&Chi[o0]) = h0;
                *reinterpret_cast<uint2*>(&Clo[o0]) = l0;
                *reinterpret_cast<uint2*>(&Chi[o1]) = h1;
                *reinterpret_cast<uint2*>(&Clo[o1]) = l1;
            } else {
                *reinterpret_cast<float2*>(&C[o0]) = y0;
                *reinterpret_cast<float2*>(&C[o1]) = y1;
            }
        }
    }
}

// r = x - u*A^T  -> writes r_hi/r_lo split  (grid (2,128), K=1024)
__global__ void __launch_bounds__(256)
mma_gemm_r(const float* __restrict__ x)
{
    mma_gemm_body<N_DIM, true, true>(g_uh, g_ul, g_Ah, g_Al, x,
                                     nullptr, g_rh, g_rl, M_DIM);
}

// v = u + P*Wi^T  (grid (8,128), K=256), P = r-split (or x-split at iter 0)
__global__ void __launch_bounds__(256)
mma_gemm_v(const uint32_t* __restrict__ Ph, const uint32_t* __restrict__ Pl,
           const uint32_t* __restrict__ Qh, const uint32_t* __restrict__ Ql,
           const float* __restrict__ u)
{
    mma_gemm_body<M_DIM, false, false>(Ph, Pl, Qh, Ql, u,
                                       g_v, nullptr, nullptr, N_DIM);
}

// ---------------------------------------------------------------------------
// Per-row exact k-th largest of |v| (4-pass MSB radix select on fp32 bits),
// masked soft-threshold, writes u (fp32) and its tf32 split u_hi/u_lo.
// ---------------------------------------------------------------------------
__global__ void __launch_bounds__(256)
select_kernel(const float* __restrict__ thr, const int it, const int k,
              float* __restrict__ u)
{
    const int row  = blockIdx.x;
    const int tid  = threadIdx.x;
    const int lane = tid & 31;

    const float4 vv = *reinterpret_cast<const float4*>(
        &g_v[(size_t)row * N_DIM + tid * 4]);
    float vals[4] = { vv.x, vv.y, vv.z, vv.w };
    unsigned bits[4];
#pragma unroll
    for (int j = 0; j < 4; ++j)
        bits[j] = __float_as_uint(vals[j]) & 0x7FFFFFFFu;

    __shared__ int hist[256];
    __shared__ unsigned s_pref;
    __shared__ int s_k;

    unsigned prefix = 0;
    int kk = k;

#pragma unroll
    for (int pass = 0; pass < 4; ++pass) {
        const int shift = 24 - 8 * pass;
        const unsigned pmask = (pass == 0) ? 0u : (0xFFFFFFFFu << (shift + 8));

        hist[tid] = 0;
        __syncthreads();

#pragma unroll
        for (int j = 0; j < 4; ++j) {
            const bool act = ((bits[j] & pmask) == prefix);
            const unsigned b = (bits[j] >> shift) & 0xFFu;
            const unsigned amask = __ballot_sync(0xFFFFFFFFu, act);
            if (act) {
                const unsigned same = __match_any_sync(amask, b);
                if (lane == (int)(__ffs(same) - 1))
                    atomicAdd(&hist[b], __popc(same));
            }
        }
        __syncthreads();

        if (tid < 32) {
            const int base = tid * 8;
            int v[8];
            int s = 0;
#pragma unroll
            for (int j = 7; j >= 0; --j) { s += hist[base + j]; v[j] = s; }
            int acc = s;                    // inclusive suffix over lanes
#pragma unroll
            for (int off = 1; off < 32; off <<= 1) {
                const int tt = __shfl_down_sync(0xFFFFFFFFu, acc, off);
                if (lane + off < 32) acc += tt;
            }
            const int above_lanes = acc - s;
#pragma unroll
            for (int j = 0; j < 8; ++j) {
                const int sfx = above_lanes + v[j];
                const int abv = above_lanes + ((j < 7) ? v[j + 1] : 0);
                if (sfx >= kk && abv < kk) {
                    s_pref = prefix | ((unsigned)(base + j) << shift);
                    s_k    = kk - abv;
                }
            }
        }
        __syncthreads();
        prefix = s_pref;
        kk     = s_k;
    }

    const float thresh = __uint_as_float(prefix);  // exact k-th largest |v|
    const float t = thr[it];

    float out[4];
    uint4 uh, ul;
#pragma unroll
    for (int j = 0; j < 4; ++j) {
        const float v  = vals[j];
        const float av = __uint_as_float(bits[j]);
        const bool  m  = (av >= t) && (av >= thresh);
        float sh = fmaxf(av - t, 0.0f);
        sh = copysignf(sh, v);
        out[j] = m ? v : sh;
    }
    split2(out[0], uh.x, ul.x);
    split2(out[1], uh.y, ul.y);
    split2(out[2], uh.z, ul.z);
    split2(out[3], uh.w, ul.w);

    const size_t base = (size_t)row * N_DIM + tid * 4;
    *reinterpret_cast<float4*>(&u[base]) =
        make_float4(out[0], out[1], out[2], out[3]);
    *reinterpret_cast<uint4*>(&g_uh[base]) = uh;
    *reinterpret_cast<uint4*>(&g_ul[base]) = ul;
}

// ---------------------------------------------------------------------------
extern "C" void kernel_launch(void* const* d_in, const int* in_sizes, int n_in,
                              void* d_out, int out_size)
{
    const float* x   = (const float*)d_in[0];   // [16384, 256]
    const float* A   = (const float*)d_in[1];   // [256, 1024]
    const float* W   = (const float*)d_in[2];   // [16, 1024, 256]
    const float* thr = (const float*)d_in[3];   // [16]
    float* u = (float*)d_out;                   // [16384, 1024]

    uint32_t *xh, *xl, *Ah, *Al, *Wh, *Wl, *rh, *rl;
    cudaGetSymbolAddress((void**)&xh, g_xh);
    cudaGetSymbolAddress((void**)&xl, g_xl);
    cudaGetSymbolAddress((void**)&Ah, g_Ah);
    cudaGetSymbolAddress((void**)&Al, g_Al);
    cudaGetSymbolAddress((void**)&Wh, g_Wh);
    cudaGetSymbolAddress((void**)&Wl, g_Wl);
    cudaGetSymbolAddress((void**)&rh, g_rh);
    cudaGetSymbolAddress((void**)&rl, g_rl);

    const int smem_bytes = 2 * 16384 * sizeof(uint32_t);   // 128 KB
    cudaFuncSetAttribute(mma_gemm_r, cudaFuncAttributeMaxDynamicSharedMemorySize,
                         smem_bytes);
    cudaFuncSetAttribute(mma_gemm_v, cudaFuncAttributeMaxDynamicSharedMemorySize,
                         smem_bytes);

    // k = 1024 - (ceil((100-p)/100 * 1024) - 1), p = min(1.2*(i+1), 5.0)
    static const int ktab[DEPTH] = {13, 25, 37, 50, 52, 52, 52, 52,
                                    52, 52, 52, 52, 52, 52, 52, 52};

    cudaMemsetAsync(u, 0, (size_t)B_ROWS * N_DIM * sizeof(float));

    // one-shot operand splits: A (256x1024), W (16x1024x256), x (16384x256)
    split_kernel<<<(M_DIM * N_DIM / 4 + 255) / 256, 256>>>(A, Ah, Al,
                                                           M_DIM * N_DIM / 4);
    split_kernel<<<(DEPTH * N_DIM * M_DIM / 4 + 255) / 256, 256>>>(
        W, Wh, Wl, DEPTH * N_DIM * M_DIM / 4);
    split_kernel<<<(B_ROWS * M_DIM / 4 + 255) / 256, 256>>>(x, xh, xl,
                                                            B_ROWS * M_DIM / 4);

    const dim3 blk(256);
    const dim3 grid_r(M_DIM / 128, B_ROWS / 128);   // (2, 128)
    const dim3 grid_v(N_DIM / 128, B_ROWS / 128);   // (8, 128)

    for (int i = 0; i < DEPTH; ++i) {
        if (i > 0)
            mma_gemm_r<<<grid_r, blk, smem_bytes>>>(x);
        const uint32_t* Ph = (i == 0) ? xh : rh;
        const uint32_t* Pl = (i == 0) ? xl : rl;
        mma_gemm_v<<<grid_v, blk, smem_bytes>>>(
            Ph, Pl, Wh + (size_t)i * N_DIM * M_DIM,
            Wl + (size_t)i * N_DIM * M_DIM, u);
        select_kernel<<<B_ROWS, blk>>>(thr, i, ktab[i], u);
    }
}

// round 13
// speedup vs baseline: 1.6989x; 1.6989x over previous
#include <cuda_runtime.h>
#include <cstdint>

#define B_ROWS 16384
#define M_DIM  256
#define N_DIM  1024
#define DEPTH  16

// ---------------------------------------------------------------------------
// Scratch (__device__ globals per allocation-free rule)
// ---------------------------------------------------------------------------
__device__ float    g_r [(size_t)B_ROWS * M_DIM];            // 16 MB
__device__ float    g_v [(size_t)B_ROWS * N_DIM];            // 64 MB
__device__ uint32_t g_Ah[(size_t)M_DIM * N_DIM];             //  1 MB
__device__ uint32_t g_Al[(size_t)M_DIM * N_DIM];             //  1 MB
__device__ uint32_t g_Wh[(size_t)DEPTH * N_DIM * M_DIM];     // 16 MB
__device__ uint32_t g_Wl[(size_t)DEPTH * N_DIM * M_DIM];     // 16 MB

// ---------------------------------------------------------------------------
// helpers
// ---------------------------------------------------------------------------
__device__ __forceinline__ uint32_t smem_u32(const void* p) {
    uint32_t a;
    asm("{ .reg .u64 t; cvta.to.shared.u64 t, %1; cvt.u32.u64 %0, t; }"
        : "=r"(a) : "l"(p));
    return a;
}

#define CP_ASYNC_16(dst, src) \
    asm volatile("cp.async.ca.shared.global [%0], [%1], 16;" \
                 :: "r"(dst), "l"(src) : "memory")
#define CP_COMMIT() asm volatile("cp.async.commit_group;" ::: "memory")

__device__ __forceinline__ uint32_t tf32_hi(float x) {
    uint32_t h;
    asm("cvt.rna.tf32.f32 %0, %1;" : "=r"(h) : "f"(x));
    return h;
}
__device__ __forceinline__ void split2(float x, uint32_t& h, uint32_t& l) {
    h = tf32_hi(x);
    l = __float_as_uint(x - __uint_as_float(h));
}

__device__ __forceinline__ void mma_tf32(float* c, const uint32_t* a,
                                         const uint32_t* b) {
    asm volatile(
        "mma.sync.aligned.m16n8k8.row.col.f32.tf32.tf32.f32 "
        "{%0,%1,%2,%3}, {%4,%5,%6,%7}, {%8,%9}, {%0,%1,%2,%3};"
        : "+f"(c[0]), "+f"(c[1]), "+f"(c[2]), "+f"(c[3])
        : "r"(a[0]), "r"(a[1]), "r"(a[2]), "r"(a[3]), "r"(b[0]), "r"(b[1]));
}

// ---------------------------------------------------------------------------
// One-shot operand split for the weight matrices A and W only
// ---------------------------------------------------------------------------
__global__ void __launch_bounds__(256)
split_kernel(const float* __restrict__ src, uint32_t* __restrict__ hi,
             uint32_t* __restrict__ lo, int n4)
{
    const int i = blockIdx.x * 256 + threadIdx.x;
    if (i >= n4) return;
    const float4 v = reinterpret_cast<const float4*>(src)[i];
    uint4 h, l;
    split2(v.x, h.x, l.x);
    split2(v.y, h.y, l.y);
    split2(v.z, h.z, l.z);
    split2(v.w, h.w, l.w);
    reinterpret_cast<uint4*>(hi)[i] = h;
    reinterpret_cast<uint4*>(lo)[i] = l;
}

// ---------------------------------------------------------------------------
// Smem stage (BK=32): A-fp32 tile (16 KB) + Bhi (16 KB) + Blo (16 KB) = 48 KB.
// Tile layout (u32 words): offset(kblk, m, klo) = kblk*512 + ((m^kblk)<<2) + klo,
// kblk=(k%32)/4 in [0,8), klo=k%4. XOR permutes 16B slots within each kblk ->
// conflict-free cp.async stores and conflict-free fragment LDS (R9-validated).
// Double-buffered: 96 KB/CTA -> 2 CTAs/SM (227 KB cap).
// ---------------------------------------------------------------------------
#define STAGE_WORDS 12288

template<int KTOT>
__device__ __forceinline__ void stage_load(const float* __restrict__ P,
                                           const uint32_t* __restrict__ Qh,
                                           const uint32_t* __restrict__ Ql,
                                           int i0, int j0, int kt,
                                           uint32_t sbase_bytes)
{
    const int tid = threadIdx.x;
    const int k0 = kt * 32;
    const uint32_t stage = sbase_bytes + (uint32_t)((kt & 1) * (STAGE_WORDS * 4));
#pragma unroll
    for (int rep = 0; rep < 4; ++rep) {
        const int c  = tid + 256 * rep;     // chunk id 0..1023
        const int m  = c >> 3;              // 0..127
        const int kb = c & 7;               // 0..7
        const uint32_t off = (uint32_t)((kb << 11) + ((m ^ kb) << 4));
        const size_t pi = (size_t)(i0 + m) * KTOT + k0 + kb * 4;
        const size_t qi = (size_t)(j0 + m) * KTOT + k0 + kb * 4;
        CP_ASYNC_16(stage + off,           P  + pi);
        CP_ASYNC_16(stage + 16384u + off,  Qh + qi);
        CP_ASYNC_16(stage + 32768u + off,  Ql + qi);
    }
    CP_COMMIT();
}

// ---------------------------------------------------------------------------
// 3xTF32 NT GEMM: C[i,j] = aux[i,j] (+/-) sum_k P[i,k]*Q[j,k]
// CTA 128x128, BK=32, 256 threads, warp tile 64x32 (warp grid 2m x 4n).
// P streamed fp32, split in registers; Q pre-split hi/lo from gmem.
// ---------------------------------------------------------------------------
template<int KTOT, bool SUB>
__device__ __forceinline__ void mma_gemm_body(const float* __restrict__ P,
                                              const uint32_t* __restrict__ Qh,
                                              const uint32_t* __restrict__ Ql,
                                              const float* __restrict__ aux,
                                              float* __restrict__ C,
                                              const int ldc)
{
    extern __shared__ __align__(16) uint32_t sm[];   // 2 x STAGE_WORDS

    const int tid  = threadIdx.x;
    const int lane = tid & 31;
    const int w    = tid >> 5;
    const int g    = lane >> 2;
    const int t    = lane & 3;
    const int i0   = blockIdx.y * 128;
    const int j0   = blockIdx.x * 128;
    const int wm   = (w >> 2) * 64;
    const int wn   = (w & 3) * 32;

    const uint32_t sbase = smem_u32(sm);

    float acc[4][4][4];
#pragma unroll
    for (int a = 0; a < 4; ++a)
#pragma unroll
        for (int b = 0; b < 4; ++b)
#pragma unroll
            for (int c = 0; c < 4; ++c) acc[a][b][c] = 0.0f;

    constexpr int NSTAGE = KTOT / 32;
    stage_load<KTOT>(P, Qh, Ql, i0, j0, 0, sbase);

#pragma unroll 1
    for (int kt = 0; kt < NSTAGE; ++kt) {
        if (kt + 1 < NSTAGE) {
            stage_load<KTOT>(P, Qh, Ql, i0, j0, kt + 1, sbase);
            asm volatile("cp.async.wait_group 1;" ::: "memory");
        } else {
            asm volatile("cp.async.wait_group 0;" ::: "memory");
        }
        __syncthreads();

        const uint32_t* As  = sm + (kt & 1) * STAGE_WORDS;   // fp32 bits
        const uint32_t* Bhs = As + 4096;
        const uint32_t* Bls = As + 8192;

#pragma unroll
        for (int ks = 0; ks < 4; ++ks) {       // four k8-pairs per stage
            const int kb0 = 2 * ks;
            const int kb1 = 2 * ks + 1;

            // A fragments (fp32 -> split in regs):
            // a0=(g,k=t) a1=(g+8,t) a2=(g,t+4) a3=(g+8,t+4)
            uint32_t ah[4][4], al[4][4];
#pragma unroll
            for (int mi = 0; mi < 4; ++mi) {
                const int m0 = wm + mi * 16 + g;
                const int m1 = m0 + 8;
                const int i00 = kb0 * 512 + ((m0 ^ kb0) << 2) + t;
                const int i01 = kb0 * 512 + ((m1 ^ kb0) << 2) + t;
                const int i10 = kb1 * 512 + ((m0 ^ kb1) << 2) + t;
                const int i11 = kb1 * 512 + ((m1 ^ kb1) << 2) + t;
                split2(__uint_as_float(As[i00]), ah[mi][0], al[mi][0]);
                split2(__uint_as_float(As[i01]), ah[mi][1], al[mi][1]);
                split2(__uint_as_float(As[i10]), ah[mi][2], al[mi][2]);
                split2(__uint_as_float(As[i11]), ah[mi][3], al[mi][3]);
            }
#pragma unroll
            for (int ni = 0; ni < 4; ++ni) {   // B hi/lo loaded directly
                const int n0 = wn + ni * 8 + g;
                const int j00 = kb0 * 512 + ((n0 ^ kb0) << 2) + t;
                const int j10 = kb1 * 512 + ((n0 ^ kb1) << 2) + t;
                uint32_t bh[2], bl[2];
                bh[0] = Bhs[j00]; bl[0] = Bls[j00];
                bh[1] = Bhs[j10]; bl[1] = Bls[j10];
#pragma unroll
                for (int mi = 0; mi < 4; ++mi) {
                    mma_tf32(acc[mi][ni], ah[mi], bh);   // hh
                    mma_tf32(acc[mi][ni], al[mi], bh);   // lh
                    mma_tf32(acc[mi][ni], ah[mi], bl);   // hl
                }
            }
        }
        __syncthreads();
    }

    // epilogue: C = aux +/- acc
    // c0=(row g, col 2t) c1=(g,2t+1) c2=(g+8,2t) c3=(g+8,2t+1)
#pragma unroll
    for (int mi = 0; mi < 4; ++mi) {
        const int r0 = i0 + wm + mi * 16 + g;
#pragma unroll
        for (int ni = 0; ni < 4; ++ni) {
            const int col = j0 + wn + ni * 8 + 2 * t;
            const size_t o0 = (size_t)r0 * ldc + col;
            const size_t o1 = (size_t)(r0 + 8) * ldc + col;
            const float2 x0 = *reinterpret_cast<const float2*>(&aux[o0]);
            const float2 x1 = *reinterpret_cast<const float2*>(&aux[o1]);
            float2 y0, y1;
            if (SUB) {
                y0.x = x0.x - acc[mi][ni][0]; y0.y = x0.y - acc[mi][ni][1];
                y1.x = x1.x - acc[mi][ni][2]; y1.y = x1.y - acc[mi][ni][3];
            } else {
                y0.x = x0.x + acc[mi][ni][0]; y0.y = x0.y + acc[mi][ni][1];
                y1.x = x1.x + acc[mi][ni][2]; y1.y = x1.y + acc[mi][ni][3];
            }
            *reinterpret_cast<float2*>(&C[o0]) = y0;
            *reinterpret_cast<float2*>(&C[o1]) = y1;
        }
    }
}

// r = x - u*A^T    (grid (2,128), K=1024)
__global__ void __launch_bounds__(256, 2)
mma_gemm_r(const float* __restrict__ u, const float* __restrict__ x)
{
    mma_gemm_body<N_DIM, true>(u, g_Ah, g_Al, x, g_r, M_DIM);
}

// v = u + P*Wi^T   (grid (8,128), K=256), P = r (or x at iter 0)
__global__ void __launch_bounds__(256, 2)
mma_gemm_v(const float* __restrict__ P, const uint32_t* __restrict__ Qh,
           const uint32_t* __restrict__ Ql, const float* __restrict__ u)
{
    mma_gemm_body<M_DIM, false>(P, Qh, Ql, u, g_v, N_DIM);
}

// ---------------------------------------------------------------------------
// Per-row exact k-th largest of |v| (4-pass MSB radix select on fp32 bits),
// then masked soft-threshold. Warp-aggregated histogram atomics + single-warp
// shfl suffix scan: 3 block barriers per pass.
// ---------------------------------------------------------------------------
__global__ void __launch_bounds__(256)
select_kernel(const float* __restrict__ thr, const int it, const int k,
              float* __restrict__ u)
{
    const int row  = blockIdx.x;
    const int tid  = threadIdx.x;
    const int lane = tid & 31;

    const float4 vv = *reinterpret_cast<const float4*>(
        &g_v[(size_t)row * N_DIM + tid * 4]);
    float vals[4] = { vv.x, vv.y, vv.z, vv.w };
    unsigned bits[4];
#pragma unroll
    for (int j = 0; j < 4; ++j)
        bits[j] = __float_as_uint(vals[j]) & 0x7FFFFFFFu;

    __shared__ int hist[256];
    __shared__ unsigned s_pref;
    __shared__ int s_k;

    unsigned prefix = 0;
    int kk = k;

#pragma unroll
    for (int pass = 0; pass < 4; ++pass) {
        const int shift = 24 - 8 * pass;
        const unsigned pmask = (pass == 0) ? 0u : (0xFFFFFFFFu << (shift + 8));

        hist[tid] = 0;
        __syncthreads();

#pragma unroll
        for (int j = 0; j < 4; ++j) {
            const bool act = ((bits[j] & pmask) == prefix);
            const unsigned b = (bits[j] >> shift) & 0xFFu;
            const unsigned amask = __ballot_sync(0xFFFFFFFFu, act);
            if (act) {
                const unsigned same = __match_any_sync(amask, b);
                if (lane == (int)(__ffs(same) - 1))
                    atomicAdd(&hist[b], __popc(same));
            }
        }
        __syncthreads();

        if (tid < 32) {
            const int base = tid * 8;
            int v[8];
            int s = 0;
#pragma unroll
            for (int j = 7; j >= 0; --j) { s += hist[base + j]; v[j] = s; }
            int acc = s;                    // inclusive suffix over lanes
#pragma unroll
            for (int off = 1; off < 32; off <<= 1) {
                const int tt = __shfl_down_sync(0xFFFFFFFFu, acc, off);
                if (lane + off < 32) acc += tt;
            }
            const int above_lanes = acc - s;
#pragma unroll
            for (int j = 0; j < 8; ++j) {
                const int sfx = above_lanes + v[j];
                const int abv = above_lanes + ((j < 7) ? v[j + 1] : 0);
                if (sfx >= kk && abv < kk) {
                    s_pref = prefix | ((unsigned)(base + j) << shift);
                    s_k    = kk - abv;
                }
            }
        }
        __syncthreads();
        prefix = s_pref;
        kk     = s_k;
    }

    const float thresh = __uint_as_float(prefix);  // exact k-th largest |v|
    const float t = thr[it];

    float out[4];
#pragma unroll
    for (int j = 0; j < 4; ++j) {
        const float v  = vals[j];
        const float av = __uint_as_float(bits[j]);
        const bool  m  = (av >= t) && (av >= thresh);
        float sh = fmaxf(av - t, 0.0f);
        sh = copysignf(sh, v);
        out[j] = m ? v : sh;
    }
    *reinterpret_cast<float4*>(&u[(size_t)row * N_DIM + tid * 4]) =
        make_float4(out[0], out[1], out[2], out[3]);
}

// ---------------------------------------------------------------------------
extern "C" void kernel_launch(void* const* d_in, const int* in_sizes, int n_in,
                              void* d_out, int out_size)
{
    const float* x   = (const float*)d_in[0];   // [16384, 256]
    const float* A   = (const float*)d_in[1];   // [256, 1024]
    const float* W   = (const float*)d_in[2];   // [16, 1024, 256]
    const float* thr = (const float*)d_in[3];   // [16]
    float* u = (float*)d_out;                   // [16384, 1024]

    float* r_ptr = nullptr;
    cudaGetSymbolAddress((void**)&r_ptr, g_r);
    uint32_t *Ah, *Al, *Wh, *Wl;
    cudaGetSymbolAddress((void**)&Ah, g_Ah);
    cudaGetSymbolAddress((void**)&Al, g_Al);
    cudaGetSymbolAddress((void**)&Wh, g_Wh);
    cudaGetSymbolAddress((void**)&Wl, g_Wl);

    const int smem_bytes = 2 * STAGE_WORDS * sizeof(uint32_t);   // 96 KB
    cudaFuncSetAttribute(mma_gemm_r, cudaFuncAttributeMaxDynamicSharedMemorySize,
                         smem_bytes);
    cudaFuncSetAttribute(mma_gemm_v, cudaFuncAttributeMaxDynamicSharedMemorySize,
                         smem_bytes);

    // k = 1024 - (ceil((100-p)/100 * 1024) - 1), p = min(1.2*(i+1), 5.0)
    static const int ktab[DEPTH] = {13, 25, 37, 50, 52, 52, 52, 52,
                                    52, 52, 52, 52, 52, 52, 52, 52};

    cudaMemsetAsync(u, 0, (size_t)B_ROWS * N_DIM * sizeof(float));

    // one-shot weight splits: A (256x1024), W (16x1024x256)
    split_kernel<<<M_DIM * N_DIM / 4 / 256, 256>>>(A, Ah, Al, M_DIM * N_DIM / 4);
    split_kernel<<<DEPTH * N_DIM * M_DIM / 4 / 256, 256>>>(
        W, Wh, Wl, DEPTH * N_DIM * M_DIM / 4);

    const dim3 blk(256);
    const dim3 grid_r(M_DIM / 128, B_ROWS / 128);   // (2, 128)
    const dim3 grid_v(N_DIM / 128, B_ROWS / 128);   // (8, 128)

    for (int i = 0; i < DEPTH; ++i) {
        if (i > 0)
            mma_gemm_r<<<grid_r, blk, smem_bytes>>>(u, x);
        const float* P = (i == 0) ? x : r_ptr;      // iter 0: u=0 -> r=x
        mma_gemm_v<<<grid_v, blk, smem_bytes>>>(
            P, Wh + (size_t)i * N_DIM * M_DIM,
            Wl + (size_t)i * N_DIM * M_DIM, u);
        select_kernel<<<B_ROWS, blk>>>(thr, i, ktab[i], u);
    }
}